// round 15
// baseline (speedup 1.0000x reference)
#include <cuda_runtime.h>
#include <cstdint>

// Problem constants
#define HW      16384
#define CIN     512
#define CH      30
#define NCLS    17
#define NBATCH  8
#define BN_EPS  1e-5f
#define GRID    296        // 2 CTAs/SM x 148 SMs -> one wave
#define TPB     128        // 4 warps
#define NTILES  2048       // 64-px tiles
#define TQ      6
#define TREM    272
#define TIE_EPS 3e-3f      // near-tie gap threshold (mma-vs-scalar logit delta << this)

// smem layout (bytes)
#define WF_OFF   0         // float [2][64][32][4] fragment-ordered weights (65536)
#define SD_OFF   65536     // float sD[64][34] (8704)
#define W1_OFF   74240     // float w1s[510]
#define B1_OFF   76280     // float b1s[17]
#define B0F_OFF  76348     // float b0f[30]
#define SMEM_BYTES 76480

// fragment-ordered folded conv0 weights + plain copy for scalar fallback
__device__ __align__(16) float g_wfrag[2][64][32][4];
__device__ __align__(16) float g_wfold[CIN * CH];     // [c][o]

__device__ __forceinline__ uint32_t f2tf(float v) {
    uint32_t r;
    asm("cvt.rna.tf32.f32 %0, %1;" : "=r"(r) : "f"(v));
    return r;
}
// EXACT 3-limb split: v == x1 + x2 + x3, each tf32-representable.
__device__ __forceinline__ void split3(float v, uint32_t& x1, uint32_t& x2, uint32_t& x3) {
    x1 = f2tf(v);
    float r = v - __uint_as_float(x1);
    x2 = f2tf(r);
    x3 = f2tf(r - __uint_as_float(x2));
}
__device__ __forceinline__ void mma8(float* acc, const uint32_t* a,
                                     uint32_t b0, uint32_t b1) {
    asm("mma.sync.aligned.m16n8k8.row.col.f32.tf32.tf32.f32 "
        "{%0,%1,%2,%3}, {%4,%5,%6,%7}, {%8,%9}, {%0,%1,%2,%3};"
        : "+f"(acc[0]), "+f"(acc[1]), "+f"(acc[2]), "+f"(acc[3])
        : "r"(a[0]), "r"(a[1]), "r"(a[2]), "r"(a[3]), "r"(b0), "r"(b1));
}

// ============ prep: BN-fold w0 into fragment order + plain [c][o] copy ============
// g_wfrag[arr][ks][lane][r]: nt = arr*2 + (r>>1), j = r&1
//   value = wfold[o = nt*8 + (lane>>2)][c = ks*8 + (lane&3) + 4*j]
__global__ void prep_kernel(const float* __restrict__ w0,
                            const float* __restrict__ gamma,
                            const float* __restrict__ var)
{
    int idx = blockIdx.x * 256 + threadIdx.x;      // 0..16383
    int r    = idx & 3;
    int lane = (idx >> 2) & 31;
    int ks   = (idx >> 7) & 63;
    int arr  = idx >> 13;
    int nt = arr * 2 + (r >> 1);
    int o  = nt * 8 + (lane >> 2);
    int c  = ks * 8 + (lane & 3) + 4 * (r & 1);
    float v = 0.0f;
    if (o < CH) {
        v = w0[o * CIN + c] * (gamma[o] * rsqrtf(var[o] + BN_EPS));
        g_wfold[c * CH + o] = v;
    }
    ((float*)g_wfrag)[idx] = v;
}

// ============ main: mma.sync tf32 conv0 + near-tie scalar fallback + epilogue ============
__global__ __launch_bounds__(TPB, 2) void mma_segnet_kernel(
    const float* __restrict__ x,
    const float* __restrict__ b0,
    const float* __restrict__ gamma,
    const float* __restrict__ beta,
    const float* __restrict__ mean,
    const float* __restrict__ var,
    const float* __restrict__ w1,
    const float* __restrict__ b1,
    float* __restrict__ dout,
    int write_logits)
{
    extern __shared__ unsigned char smem[];
    const float4* wfA = (const float4*)(smem + WF_OFF);            // [64][32] float4
    const float4* wfB = (const float4*)(smem + WF_OFF + 32768);
    float* sD  = (float*)(smem + SD_OFF);                          // [64][34]
    float* w1s = (float*)(smem + W1_OFF);
    float* b1s = (float*)(smem + B1_OFF);
    float* b0f = (float*)(smem + B0F_OFF);

    const int tid  = threadIdx.x;
    const int w    = tid >> 5;
    const int lane = tid & 31;

    {
        const float4* src = (const float4*)g_wfrag;
        float4* dst = (float4*)(smem + WF_OFF);
#pragma unroll 8
        for (int i = tid; i < 4096; i += TPB) dst[i] = src[i];
    }
    for (int i = tid; i < NCLS * CH; i += TPB) w1s[i] = w1[i];
    if (tid < NCLS) b1s[tid] = b1[tid];
    if (tid < CH) {
        float sc = gamma[tid] * rsqrtf(var[tid] + BN_EPS);
        b0f[tid] = (b0[tid] - mean[tid]) * sc + beta[tid];
    }
    __syncthreads();

    const int ct    = blockIdx.x;
    const int cnt   = TQ + (ct < TREM ? 1 : 0);
    const int first = ct * TQ + (ct < TREM ? ct : TREM);

    const int q = lane >> 2;
    const int g = lane & 3;

    for (int r = 0; r < cnt; r++) {
        const int px0 = (first + r) << 6;
        const int b   = px0 >> 14;
        const int hw0 = px0 & (HW - 1);

        const float* xw = x + (size_t)b * CIN * HW + hw0 + (w << 4) + q;

        float acc[4][4];
#pragma unroll
        for (int nt = 0; nt < 4; nt++)
#pragma unroll
            for (int i = 0; i < 4; i++) acc[nt][i] = 0.0f;

        float4 abuf[4];
#pragma unroll
        for (int p = 0; p < 4; p++) {
            const float* ap = xw + (size_t)((p << 3) + g) * HW;
            abuf[p] = make_float4(ap[0], ap[8], ap[4 * HW], ap[4 * HW + 8]);
        }

#pragma unroll 4
        for (int ks = 0; ks < 64; ks++) {
            float4 av = abuf[ks & 3];
            uint32_t a1[4], a2[4], a3[4];
            split3(av.x, a1[0], a2[0], a3[0]);
            split3(av.y, a1[1], a2[1], a3[1]);
            split3(av.z, a1[2], a2[2], a3[2]);
            split3(av.w, a1[3], a2[3], a3[3]);
            if (ks < 60) {
                const float* ap = xw + (size_t)(((ks + 4) << 3) + g) * HW;
                abuf[ks & 3] = make_float4(ap[0], ap[8], ap[4 * HW], ap[4 * HW + 8]);
            }
            float4 wa = wfA[ks * 32 + lane];
            float4 wb = wfB[ks * 32 + lane];
            uint32_t b1r[8], b2r[8], b3r[8];
            split3(wa.x, b1r[0], b2r[0], b3r[0]);
            split3(wa.y, b1r[1], b2r[1], b3r[1]);
            split3(wa.z, b1r[2], b2r[2], b3r[2]);
            split3(wa.w, b1r[3], b2r[3], b3r[3]);
            split3(wb.x, b1r[4], b2r[4], b3r[4]);
            split3(wb.y, b1r[5], b2r[5], b3r[5]);
            split3(wb.z, b1r[6], b2r[6], b3r[6]);
            split3(wb.w, b1r[7], b2r[7], b3r[7]);
#pragma unroll
            for (int nt = 0; nt < 4; nt++) {
                const int e = 2 * nt, o = 2 * nt + 1;
                mma8(acc[nt], a1, b1r[e], b1r[o]);   // hi*hi
                mma8(acc[nt], a1, b2r[e], b2r[o]);   // hi*mid
                mma8(acc[nt], a2, b1r[e], b1r[o]);   // mid*hi
                mma8(acc[nt], a2, b2r[e], b2r[o]);   // mid*mid
                mma8(acc[nt], a1, b3r[e], b3r[o]);   // hi*lo
                mma8(acc[nt], a3, b1r[e], b1r[o]);   // lo*hi
            }
        }

        // ---- D-stage: acc -> sD[px_local][ch] ----
        {
            float* row0 = sD + ((w << 4) + q) * 34;
            float* row8 = row0 + 8 * 34;
#pragma unroll
            for (int nt = 0; nt < 4; nt++) {
                const int col = nt * 8 + 2 * g;
                *(float2*)(row0 + col) = make_float2(acc[nt][0], acc[nt][1]);
                *(float2*)(row8 + col) = make_float2(acc[nt][2], acc[nt][3]);
            }
        }
        __syncthreads();

        // ---- epilogue with near-tie scalar fallback ----
        {
            const int px_l = tid & 63;
            const int hwp  = hw0 + px_l;
            const float* hrow = sD + px_l * 34;
            float h[CH];
#pragma unroll
            for (int j = 0; j < CH; j++)
                h[j] = fmaxf(hrow[j] + b0f[j], 0.0f);

            float lo[NCLS];
            float best = -__builtin_huge_valf(), second = -__builtin_huge_valf();
            int cls = 0;
#pragma unroll
            for (int k = 0; k < NCLS; k++) {
                float sv = b1s[k];
#pragma unroll
                for (int j = 0; j < CH; j++)
                    sv = fmaf(w1s[k * CH + j], h[j], sv);
                lo[k] = sv;
                if (sv > best) { second = best; best = sv; cls = k; }
                else if (sv > second) { second = sv; }
            }

            if (best - second < TIE_EPS) {
                // Recompute h with bit-exactly the scalar (R8) arithmetic:
                // sequential ascending-c fp32 FMA chains on the same folded weights.
                const float* xp = x + (size_t)b * CIN * HW + hwp;
#pragma unroll
                for (int j = 0; j < CH; j++) h[j] = b0f[j];
                for (int c = 0; c < CIN; c++) {
                    float xv = __ldcs(xp + (size_t)c * HW);
                    const float* wr = g_wfold + c * CH;
#pragma unroll
                    for (int j = 0; j < CH; j++)
                        h[j] = fmaf(wr[j], xv, h[j]);
                }
#pragma unroll
                for (int j = 0; j < CH; j++) h[j] = fmaxf(h[j], 0.0f);
                best = -__builtin_huge_valf();
                cls = 0;
#pragma unroll
                for (int k = 0; k < NCLS; k++) {
                    float sv = b1s[k];
#pragma unroll
                    for (int j = 0; j < CH; j++)
                        sv = fmaf(w1s[k * CH + j], h[j], sv);
                    lo[k] = sv;
                    if (sv > best) { best = sv; cls = k; }   // strict > == first-max
                }
            }

            if (write_logits && tid < 64) {
                float* lg = dout + (size_t)NBATCH * (NCLS * CH) * HW
                                 + ((size_t)b * NCLS) * HW + hwp;
#pragma unroll
                for (int k = 0; k < NCLS; k++)
                    __stcs(lg + (size_t)k * HW, lo[k]);
            }

            float* res = dout + ((size_t)b * (NCLS * CH)) * HW + hwp;
            const int j0 = (tid < 64) ? 0 : 15;
            const int j1 = (tid < 64) ? 15 : CH;
#pragma unroll
            for (int k = 0; k < NCLS; k++) {
                const bool m = (k == cls);
                for (int j = j0; j < j1; j++)
                    __stcs(res + (size_t)(k * CH + j) * HW, m ? h[j] : 0.0f);
            }
        }
        __syncthreads();
    }
}

extern "C" void kernel_launch(void* const* d_in, const int* in_sizes, int n_in,
                              void* d_out, int out_size)
{
    const float* x     = (const float*)d_in[0];
    const float* w0    = (const float*)d_in[1];
    const float* b0    = (const float*)d_in[2];
    const float* gamma = (const float*)d_in[3];
    const float* beta  = (const float*)d_in[4];
    const float* mean  = (const float*)d_in[5];
    const float* var   = (const float*)d_in[6];
    const float* w1    = (const float*)d_in[7];
    const float* b1    = (const float*)d_in[8];

    const long long res_elems   = (long long)NBATCH * NCLS * CH * HW;
    const long long total_elems = res_elems + (long long)NBATCH * NCLS * HW;
    const int write_logits = ((long long)out_size >= total_elems) ? 1 : 0;

    static int configured = 0;
    if (!configured) {
        cudaFuncSetAttribute(mma_segnet_kernel,
                             cudaFuncAttributeMaxDynamicSharedMemorySize, SMEM_BYTES);
        configured = 1;
    }

    prep_kernel<<<64, 256>>>(w0, gamma, var);
    mma_segnet_kernel<<<GRID, TPB, SMEM_BYTES>>>(
        x, b0, gamma, beta, mean, var, w1, b1, (float*)d_out, write_logits);
}

// round 16
// speedup vs baseline: 1.9039x; 1.9039x over previous
#include <cuda_runtime.h>
#include <cstdint>

// Problem constants
#define HW      16384
#define CIN     512
#define CH      30
#define NCLS    17
#define NBATCH  8
#define BN_EPS  1e-5f
#define GRID    296        // 2 CTAs/SM x 148 SMs -> one wave
#define TPB     128        // 4 warps
#define NTILES  2048       // 64-px tiles
#define TQ      6
#define TREM    272
// MMA-vs-scalar logit delta is ~3e-6 (6-term exact limb split); 2e-5 gives 6x margin
// while triggering the scalar fallback on only ~1e-4 of pixels.
#define TIE_EPS 2e-5f

// smem layout (bytes)
#define WF_OFF   0         // float [2][64][32][4] fragment-ordered weights (65536)
#define SD_OFF   65536     // float sD[64][34] (8704)
#define W1_OFF   74240     // float w1s[510]
#define B1_OFF   76280     // float b1s[17]
#define B0F_OFF  76348     // float b0f[30]
#define SMEM_BYTES 76480

// fragment-ordered folded conv0 weights + plain copy for scalar fallback
__device__ __align__(16) float g_wfrag[2][64][32][4];
__device__ __align__(16) float g_wfold[CIN * CH];     // [c][o]

__device__ __forceinline__ uint32_t f2tf(float v) {
    uint32_t r;
    asm("cvt.rna.tf32.f32 %0, %1;" : "=r"(r) : "f"(v));
    return r;
}
// EXACT 3-limb split: v == x1 + x2 + x3, each tf32-representable.
__device__ __forceinline__ void split3(float v, uint32_t& x1, uint32_t& x2, uint32_t& x3) {
    x1 = f2tf(v);
    float r = v - __uint_as_float(x1);
    x2 = f2tf(r);
    x3 = f2tf(r - __uint_as_float(x2));
}
__device__ __forceinline__ void mma8(float* acc, const uint32_t* a,
                                     uint32_t b0, uint32_t b1) {
    asm("mma.sync.aligned.m16n8k8.row.col.f32.tf32.tf32.f32 "
        "{%0,%1,%2,%3}, {%4,%5,%6,%7}, {%8,%9}, {%0,%1,%2,%3};"
        : "+f"(acc[0]), "+f"(acc[1]), "+f"(acc[2]), "+f"(acc[3])
        : "r"(a[0]), "r"(a[1]), "r"(a[2]), "r"(a[3]), "r"(b0), "r"(b1));
}

// ============ prep: BN-fold w0 into fragment order + plain [c][o] copy ============
// g_wfrag[arr][ks][lane][r]: nt = arr*2 + (r>>1), j = r&1
//   value = wfold[o = nt*8 + (lane>>2)][c = ks*8 + (lane&3) + 4*j]
__global__ void prep_kernel(const float* __restrict__ w0,
                            const float* __restrict__ gamma,
                            const float* __restrict__ var)
{
    int idx = blockIdx.x * 256 + threadIdx.x;      // 0..16383
    int r    = idx & 3;
    int lane = (idx >> 2) & 31;
    int ks   = (idx >> 7) & 63;
    int arr  = idx >> 13;
    int nt = arr * 2 + (r >> 1);
    int o  = nt * 8 + (lane >> 2);
    int c  = ks * 8 + (lane & 3) + 4 * (r & 1);
    float v = 0.0f;
    if (o < CH) {
        v = w0[o * CIN + c] * (gamma[o] * rsqrtf(var[o] + BN_EPS));
        g_wfold[c * CH + o] = v;
    }
    ((float*)g_wfrag)[idx] = v;
}

// ============ main: mma.sync tf32 conv0 + near-tie scalar fallback + epilogue ============
__global__ __launch_bounds__(TPB, 2) void mma_segnet_kernel(
    const float* __restrict__ x,
    const float* __restrict__ b0,
    const float* __restrict__ gamma,
    const float* __restrict__ beta,
    const float* __restrict__ mean,
    const float* __restrict__ var,
    const float* __restrict__ w1,
    const float* __restrict__ b1,
    float* __restrict__ dout,
    int write_logits)
{
    extern __shared__ unsigned char smem[];
    const float4* wfA = (const float4*)(smem + WF_OFF);            // [64][32] float4
    const float4* wfB = (const float4*)(smem + WF_OFF + 32768);
    float* sD  = (float*)(smem + SD_OFF);                          // [64][34]
    float* w1s = (float*)(smem + W1_OFF);
    float* b1s = (float*)(smem + B1_OFF);
    float* b0f = (float*)(smem + B0F_OFF);

    const int tid  = threadIdx.x;
    const int w    = tid >> 5;
    const int lane = tid & 31;

    {
        const float4* src = (const float4*)g_wfrag;
        float4* dst = (float4*)(smem + WF_OFF);
#pragma unroll 8
        for (int i = tid; i < 4096; i += TPB) dst[i] = src[i];
    }
    for (int i = tid; i < NCLS * CH; i += TPB) w1s[i] = w1[i];
    if (tid < NCLS) b1s[tid] = b1[tid];
    if (tid < CH) {
        float sc = gamma[tid] * rsqrtf(var[tid] + BN_EPS);
        b0f[tid] = (b0[tid] - mean[tid]) * sc + beta[tid];
    }
    __syncthreads();

    const int ct    = blockIdx.x;
    const int cnt   = TQ + (ct < TREM ? 1 : 0);
    const int first = ct * TQ + (ct < TREM ? ct : TREM);

    const int q = lane >> 2;
    const int g = lane & 3;

    for (int r = 0; r < cnt; r++) {
        const int px0 = (first + r) << 6;
        const int b   = px0 >> 14;
        const int hw0 = px0 & (HW - 1);

        const float* xw = x + (size_t)b * CIN * HW + hw0 + (w << 4) + q;

        float acc[4][4];
#pragma unroll
        for (int nt = 0; nt < 4; nt++)
#pragma unroll
            for (int i = 0; i < 4; i++) acc[nt][i] = 0.0f;

        float4 abuf[4];
#pragma unroll
        for (int p = 0; p < 4; p++) {
            const float* ap = xw + (size_t)((p << 3) + g) * HW;
            abuf[p] = make_float4(ap[0], ap[8], ap[4 * HW], ap[4 * HW + 8]);
        }

#pragma unroll 4
        for (int ks = 0; ks < 64; ks++) {
            float4 av = abuf[ks & 3];
            uint32_t a1[4], a2[4], a3[4];
            split3(av.x, a1[0], a2[0], a3[0]);
            split3(av.y, a1[1], a2[1], a3[1]);
            split3(av.z, a1[2], a2[2], a3[2]);
            split3(av.w, a1[3], a2[3], a3[3]);
            if (ks < 60) {
                const float* ap = xw + (size_t)(((ks + 4) << 3) + g) * HW;
                abuf[ks & 3] = make_float4(ap[0], ap[8], ap[4 * HW], ap[4 * HW + 8]);
            }
            float4 wa = wfA[ks * 32 + lane];
            float4 wb = wfB[ks * 32 + lane];
            uint32_t b1r[8], b2r[8], b3r[8];
            split3(wa.x, b1r[0], b2r[0], b3r[0]);
            split3(wa.y, b1r[1], b2r[1], b3r[1]);
            split3(wa.z, b1r[2], b2r[2], b3r[2]);
            split3(wa.w, b1r[3], b2r[3], b3r[3]);
            split3(wb.x, b1r[4], b2r[4], b3r[4]);
            split3(wb.y, b1r[5], b2r[5], b3r[5]);
            split3(wb.z, b1r[6], b2r[6], b3r[6]);
            split3(wb.w, b1r[7], b2r[7], b3r[7]);
#pragma unroll
            for (int nt = 0; nt < 4; nt++) {
                const int e = 2 * nt, o = 2 * nt + 1;
                mma8(acc[nt], a1, b1r[e], b1r[o]);   // hi*hi
                mma8(acc[nt], a1, b2r[e], b2r[o]);   // hi*mid
                mma8(acc[nt], a2, b1r[e], b1r[o]);   // mid*hi
                mma8(acc[nt], a2, b2r[e], b2r[o]);   // mid*mid
                mma8(acc[nt], a1, b3r[e], b3r[o]);   // hi*lo
                mma8(acc[nt], a3, b1r[e], b1r[o]);   // lo*hi
            }
        }

        // ---- D-stage: acc -> sD[px_local][ch] ----
        {
            float* row0 = sD + ((w << 4) + q) * 34;
            float* row8 = row0 + 8 * 34;
#pragma unroll
            for (int nt = 0; nt < 4; nt++) {
                const int col = nt * 8 + 2 * g;
                *(float2*)(row0 + col) = make_float2(acc[nt][0], acc[nt][1]);
                *(float2*)(row8 + col) = make_float2(acc[nt][2], acc[nt][3]);
            }
        }
        __syncthreads();

        // ---- epilogue with (rare) near-tie scalar fallback ----
        {
            const int px_l = tid & 63;
            const int hwp  = hw0 + px_l;
            const float* hrow = sD + px_l * 34;
            float h[CH];
#pragma unroll
            for (int j = 0; j < CH; j++)
                h[j] = fmaxf(hrow[j] + b0f[j], 0.0f);

            float lo[NCLS];
            float best = -__builtin_huge_valf(), second = -__builtin_huge_valf();
            int cls = 0;
#pragma unroll
            for (int k = 0; k < NCLS; k++) {
                float sv = b1s[k];
#pragma unroll
                for (int j = 0; j < CH; j++)
                    sv = fmaf(w1s[k * CH + j], h[j], sv);
                lo[k] = sv;
                if (sv > best) { second = best; best = sv; cls = k; }
                else if (sv > second) { second = sv; }
            }

            if (best - second < TIE_EPS) {
                // Rare: recompute h with bit-exactly the scalar (R8) arithmetic —
                // ascending-c fp32 FMA chains on identical folded weights.
                // (8-wide load batching changes MLP only, not accumulation order.)
                const float* xp = x + (size_t)b * CIN * HW + hwp;
#pragma unroll
                for (int j = 0; j < CH; j++) h[j] = b0f[j];
                for (int c0 = 0; c0 < CIN; c0 += 8) {
                    float xv[8];
#pragma unroll
                    for (int i = 0; i < 8; i++)
                        xv[i] = __ldcs(xp + (size_t)(c0 + i) * HW);
#pragma unroll
                    for (int i = 0; i < 8; i++) {
                        const float* wr = g_wfold + (c0 + i) * CH;
#pragma unroll
                        for (int j = 0; j < CH; j++)
                            h[j] = fmaf(wr[j], xv[i], h[j]);
                    }
                }
#pragma unroll
                for (int j = 0; j < CH; j++) h[j] = fmaxf(h[j], 0.0f);
                best = -__builtin_huge_valf();
                cls = 0;
#pragma unroll
                for (int k = 0; k < NCLS; k++) {
                    float sv = b1s[k];
#pragma unroll
                    for (int j = 0; j < CH; j++)
                        sv = fmaf(w1s[k * CH + j], h[j], sv);
                    lo[k] = sv;
                    if (sv > best) { best = sv; cls = k; }   // strict > == first-max
                }
            }

            if (write_logits && tid < 64) {
                float* lg = dout + (size_t)NBATCH * (NCLS * CH) * HW
                                 + ((size_t)b * NCLS) * HW + hwp;
#pragma unroll
                for (int k = 0; k < NCLS; k++)
                    __stcs(lg + (size_t)k * HW, lo[k]);
            }

            float* res = dout + ((size_t)b * (NCLS * CH)) * HW + hwp;
            const int j0 = (tid < 64) ? 0 : 15;
            const int j1 = (tid < 64) ? 15 : CH;
#pragma unroll
            for (int k = 0; k < NCLS; k++) {
                const bool m = (k == cls);
                for (int j = j0; j < j1; j++)
                    __stcs(res + (size_t)(k * CH + j) * HW, m ? h[j] : 0.0f);
            }
        }
        __syncthreads();
    }
}

extern "C" void kernel_launch(void* const* d_in, const int* in_sizes, int n_in,
                              void* d_out, int out_size)
{
    const float* x     = (const float*)d_in[0];
    const float* w0    = (const float*)d_in[1];
    const float* b0    = (const float*)d_in[2];
    const float* gamma = (const float*)d_in[3];
    const float* beta  = (const float*)d_in[4];
    const float* mean  = (const float*)d_in[5];
    const float* var   = (const float*)d_in[6];
    const float* w1    = (const float*)d_in[7];
    const float* b1    = (const float*)d_in[8];

    const long long res_elems   = (long long)NBATCH * NCLS * CH * HW;
    const long long total_elems = res_elems + (long long)NBATCH * NCLS * HW;
    const int write_logits = ((long long)out_size >= total_elems) ? 1 : 0;

    static int configured = 0;
    if (!configured) {
        cudaFuncSetAttribute(mma_segnet_kernel,
                             cudaFuncAttributeMaxDynamicSharedMemorySize, SMEM_BYTES);
        configured = 1;
    }

    prep_kernel<<<64, 256>>>(w0, gamma, var);
    mma_segnet_kernel<<<GRID, TPB, SMEM_BYTES>>>(
        x, b0, gamma, beta, mean, var, w1, b1, (float*)d_out, write_logits);
}